// round 2
// baseline (speedup 1.0000x reference)
#include <cuda_runtime.h>
#include <math.h>

#define N_ENT 200000
#define N_USR 100000
#define D     64
#define NEDGE 1500000
#define NINT  1000000
#define NVIRT 3
#define NRELM1 10
#define EPSV  1e-12f

// ---------------- scratch (static device globals; no runtime alloc) ----------
__device__ float g_acc[(size_t)NVIRT * N_ENT * D];   // segment-sum accumulators (3 virt rel)
__device__ float g_u[(size_t)NVIRT * N_ENT * D];     // per-virt entity LWS state u_i
__device__ float g_entA[(size_t)N_ENT * D];          // entity ping
__device__ float g_entB[(size_t)N_ENT * D];          // entity pong
__device__ float g_usrA[(size_t)N_USR * D];
__device__ float g_usrB[(size_t)N_USR * D];
__device__ float g_accu[(size_t)N_USR * D];          // user accumulator
__device__ float g_uu[(size_t)N_USR * D];            // user LWS state
__device__ float g_s[NEDGE];                         // cumulative per-edge scalar
__device__ int   g_et[NEDGE];                        // virtual-relation id per edge
__device__ float g_invden[NVIRT * N_ENT];            // 1/max(cnt,1) per (virt, entity)
__device__ float g_invcnt[N_USR];                    // 1/max(cnt,1) per user
__device__ int   g_remap[NRELM1];
__device__ float g_w[2 * 3];                         // softmaxed agg weights per hop

// ---------------- tiny prep: relation routing + softmax(agg_w) ---------------
__global__ void k_prep(const float* __restrict__ latent,
                       const float* __restrict__ relw,
                       const float* __restrict__ aggw) {
    int t = threadIdx.x;
    if (t < NRELM1) {
        float best = -1e30f; int bi = 0;
        for (int v = 0; v < NVIRT; v++) {
            float s = 0.f;
            for (int d = 0; d < D; d++) s += relw[t * D + d] * latent[v * D + d];
            if (s > best) { best = s; bi = v; }   // first-max, matches jnp.argmax
        }
        g_remap[t] = bi;
    }
    if (t >= 32 && t < 34) {
        int h = t - 32;
        float a0 = aggw[h * 3 + 0], a1 = aggw[h * 3 + 1], a2 = aggw[h * 3 + 2];
        float m = fmaxf(a0, fmaxf(a1, a2));
        float e0 = expf(a0 - m), e1 = expf(a1 - m), e2 = expf(a2 - m);
        float s = e0 + e1 + e2;
        g_w[h * 3 + 0] = e0 / s; g_w[h * 3 + 1] = e1 / s; g_w[h * 3 + 2] = e2 / s;
    }
}

__global__ void k_et(const int* __restrict__ etype) {
    int e = blockIdx.x * blockDim.x + threadIdx.x;
    if (e < NEDGE) g_et[e] = g_remap[etype[e] - 1];
}

__global__ void k_count_ent(const int* __restrict__ head) {
    int e = blockIdx.x * blockDim.x + threadIdx.x;
    if (e < NEDGE) atomicAdd(&g_invden[g_et[e] * N_ENT + head[e]], 1.0f);
}

__global__ void k_count_usr(const int* __restrict__ uidx) {
    int j = blockIdx.x * blockDim.x + threadIdx.x;
    if (j < NINT) atomicAdd(&g_invcnt[uidx[j]], 1.0f);
}

__global__ void k_invert_ent() {
    int i = blockIdx.x * blockDim.x + threadIdx.x;
    if (i < NVIRT * N_ENT) g_invden[i] = 1.0f / fmaxf(g_invden[i], 1.0f);
}

__global__ void k_invert_usr() {
    int i = blockIdx.x * blockDim.x + threadIdx.x;
    if (i < N_USR) g_invcnt[i] = 1.0f / fmaxf(g_invcnt[i], 1.0f);
}

// ---------------- entity edge pass: fused dot + scalar update + scatter ------
// warp per edge; lane owns dims (2l, 2l+1)
template <int IT>
__global__ void k_edge_ent(const int* __restrict__ head, const int* __restrict__ tail,
                           const float* __restrict__ ent) {
    int w = (blockIdx.x * blockDim.x + threadIdx.x) >> 5;
    int lane = threadIdx.x & 31;
    if (w >= NEDGE) return;
    int i = g_et[w];
    int h = head[w], t = tail[w];
    float2 x = *(const float2*)(ent + (size_t)t * D + lane * 2);
    float coef = 1.0f;
    if (IT > 0) {
        const float* up = g_u + ((size_t)i * N_ENT + h) * D;
        float2 u2 = *(const float2*)(up + lane * 2);
        float p = u2.x * x.x + u2.y * x.y;
        #pragma unroll
        for (int o = 16; o; o >>= 1) p += __shfl_xor_sync(0xffffffffu, p, o);
        if (IT == 1) {
            if (lane == 0) g_s[w] = p;      // s1 = sim
            coef = p;
        } else {
            float s = g_s[w];
            coef = s * s * p;                // s2 = s1^2 * dot(u1, x)
        }
    }
    float* ap = g_acc + ((size_t)i * N_ENT + h) * D + lane * 2;
    float2 v; v.x = coef * x.x; v.y = coef * x.y;
    atomicAdd((float2*)ap, v);
}

// ---------------- entity row pass (iters 0,1): scale + squash + residual -----
__global__ void k_row_sq_ent(const float* __restrict__ ent) {
    int row = (blockIdx.x * blockDim.x + threadIdx.x) >> 5;   // 0 .. 3*N_ENT
    int lane = threadIdx.x & 31;
    if (row >= NVIRT * N_ENT) return;
    int i = row / N_ENT;
    int n = row - i * N_ENT;
    float inv = g_invden[row];
    float2 a = *(const float2*)(g_acc + (size_t)row * D + lane * 2);
    a.x *= inv; a.y *= inv;
    float sq = a.x * a.x + a.y * a.y;
    #pragma unroll
    for (int o = 16; o; o >>= 1) sq += __shfl_xor_sync(0xffffffffu, sq, o);
    float nrm = sqrtf(sq);
    float f = (sq / (sq + 1.0f)) / fmaxf(nrm, EPSV);          // squash factor
    float2 e = *(const float2*)(ent + (size_t)n * D + lane * 2);
    float2 o2; o2.x = a.x * f + e.x; o2.y = a.y * f + e.y;
    *(float2*)(g_u + (size_t)row * D + lane * 2) = o2;
}

// ---------------- entity final row pass: agg + l2norm + residual -------------
__global__ void k_row_final_ent(const float* __restrict__ ent, float* __restrict__ ent_out,
                                float* __restrict__ out, int hop) {
    int n = (blockIdx.x * blockDim.x + threadIdx.x) >> 5;
    int lane = threadIdx.x & 31;
    if (n >= N_ENT) return;
    float2 e = *(const float2*)(ent + (size_t)n * D + lane * 2);
    float2 agg; agg.x = 0.f; agg.y = 0.f;
    #pragma unroll
    for (int i = 0; i < NVIRT; i++) {
        float inv = g_invden[i * N_ENT + n];
        float2 a = *(const float2*)(g_acc + ((size_t)i * N_ENT + n) * D + lane * 2);
        float wv = g_w[hop * 3 + i];
        agg.x += wv * (a.x * inv + e.x);       // last iter: no squash, +ent
        agg.y += wv * (a.y * inv + e.y);
    }
    float sq = agg.x * agg.x + agg.y * agg.y;
    #pragma unroll
    for (int o = 16; o; o >>= 1) sq += __shfl_xor_sync(0xffffffffu, sq, o);
    float f = 1.0f / fmaxf(sqrtf(sq), EPSV);
    float2 o2; o2.x = agg.x * f; o2.y = agg.y * f;
    *(float2*)(ent_out + (size_t)n * D + lane * 2) = o2;
    float* op = out + (size_t)n * D + lane * 2;
    float2 prev = *(float2*)op;
    prev.x += o2.x; prev.y += o2.y;
    *(float2*)op = prev;
}

// ---------------- user edge pass ---------------------------------------------
template <int IT>
__global__ void k_edge_usr(const int* __restrict__ uidx, const int* __restrict__ iidx,
                           const float* __restrict__ ent) {
    int w = (blockIdx.x * blockDim.x + threadIdx.x) >> 5;
    int lane = threadIdx.x & 31;
    if (w >= NINT) return;
    int u = uidx[w], it = iidx[w];
    float2 x = *(const float2*)(ent + (size_t)it * D + lane * 2);
    float coef = 1.0f;
    if (IT > 0) {
        float2 u2 = *(const float2*)(g_uu + (size_t)u * D + lane * 2);
        float p = u2.x * x.x + u2.y * x.y;
        #pragma unroll
        for (int o = 16; o; o >>= 1) p += __shfl_xor_sync(0xffffffffu, p, o);
        coef = p;                               // fresh sim each iter (not cumulative)
    }
    float* ap = g_accu + (size_t)u * D + lane * 2;
    float2 v; v.x = coef * x.x; v.y = coef * x.y;
    atomicAdd((float2*)ap, v);
}

__global__ void k_row_sq_usr(const float* __restrict__ usr) {
    int n = (blockIdx.x * blockDim.x + threadIdx.x) >> 5;
    int lane = threadIdx.x & 31;
    if (n >= N_USR) return;
    float inv = g_invcnt[n];
    float2 a = *(const float2*)(g_accu + (size_t)n * D + lane * 2);
    a.x *= inv; a.y *= inv;
    float sq = a.x * a.x + a.y * a.y;
    #pragma unroll
    for (int o = 16; o; o >>= 1) sq += __shfl_xor_sync(0xffffffffu, sq, o);
    float nrm = sqrtf(sq);
    float f = (sq / (sq + 1.0f)) / fmaxf(nrm, EPSV);
    float2 e = *(const float2*)(usr + (size_t)n * D + lane * 2);
    float2 o2; o2.x = a.x * f + e.x; o2.y = a.y * f + e.y;
    *(float2*)(g_uu + (size_t)n * D + lane * 2) = o2;
}

__global__ void k_row_final_usr(const float* __restrict__ usr, float* __restrict__ usr_out,
                                float* __restrict__ out_usr) {
    int n = (blockIdx.x * blockDim.x + threadIdx.x) >> 5;
    int lane = threadIdx.x & 31;
    if (n >= N_USR) return;
    float inv = g_invcnt[n];
    float2 a = *(const float2*)(g_accu + (size_t)n * D + lane * 2);
    float2 e = *(const float2*)(usr + (size_t)n * D + lane * 2);
    float2 v; v.x = a.x * inv + e.x; v.y = a.y * inv + e.y;
    float sq = v.x * v.x + v.y * v.y;
    #pragma unroll
    for (int o = 16; o; o >>= 1) sq += __shfl_xor_sync(0xffffffffu, sq, o);
    float f = 1.0f / fmaxf(sqrtf(sq), EPSV);
    float2 o2; o2.x = v.x * f; o2.y = v.y * f;
    *(float2*)(usr_out + (size_t)n * D + lane * 2) = o2;
    float* op = out_usr + (size_t)n * D + lane * 2;
    float2 prev = *(float2*)op;
    prev.x += o2.x; prev.y += o2.y;
    *(float2*)op = prev;
}

// ---------------- host orchestration -----------------------------------------
extern "C" void kernel_launch(void* const* d_in, const int* in_sizes, int n_in,
                              void* d_out, int out_size) {
    (void)in_sizes; (void)n_in; (void)out_size;
    const float* entity_emb = (const float*)d_in[0];
    const float* user_emb   = (const float*)d_in[1];
    const float* latent     = (const float*)d_in[2];
    const float* relw       = (const float*)d_in[3];
    const float* aggw       = (const float*)d_in[4];
    const int*   eidx       = (const int*)d_in[5];
    const int*   etype      = (const int*)d_in[6];
    const int*   uidx       = (const int*)d_in[7];
    const int*   iidx       = (const int*)d_in[8];
    float* out = (float*)d_out;
    const int* head = eidx;
    const int* tail = eidx + NEDGE;

    void *p_acc, *p_accu, *p_invden, *p_invcnt, *p_entA, *p_entB, *p_usrA, *p_usrB;
    cudaGetSymbolAddress(&p_acc,    g_acc);
    cudaGetSymbolAddress(&p_accu,   g_accu);
    cudaGetSymbolAddress(&p_invden, g_invden);
    cudaGetSymbolAddress(&p_invcnt, g_invcnt);
    cudaGetSymbolAddress(&p_entA,   g_entA);
    cudaGetSymbolAddress(&p_entB,   g_entB);
    cudaGetSymbolAddress(&p_usrA,   g_usrA);
    cudaGetSymbolAddress(&p_usrB,   g_usrB);

    const int TPB = 256;
    const int EB  = (NEDGE * 32 + TPB - 1) / TPB;        // warp per edge
    const int IB  = (NINT  * 32 + TPB - 1) / TPB;        // warp per interaction
    const int RB3 = (NVIRT * N_ENT * 32 + TPB - 1) / TPB;
    const int RB  = (N_ENT * 32 + TPB - 1) / TPB;
    const int UB  = (N_USR * 32 + TPB - 1) / TPB;
    const int ET  = (NEDGE + TPB - 1) / TPB;
    const int IT_ = (NINT + TPB - 1) / TPB;

    // prep (stateless: recomputed every call)
    k_prep<<<1, 64>>>(latent, relw, aggw);
    k_et<<<ET, TPB>>>(etype);
    cudaMemsetAsync(p_invden, 0, (size_t)NVIRT * N_ENT * sizeof(float), 0);
    cudaMemsetAsync(p_invcnt, 0, (size_t)N_USR * sizeof(float), 0);
    k_count_ent<<<ET, TPB>>>(head);
    k_count_usr<<<IT_, TPB>>>(uidx);
    k_invert_ent<<<(NVIRT * N_ENT + TPB - 1) / TPB, TPB>>>();
    k_invert_usr<<<(N_USR + TPB - 1) / TPB, TPB>>>();

    size_t entB_ = (size_t)N_ENT * D * sizeof(float);
    size_t usrB_ = (size_t)N_USR * D * sizeof(float);
    cudaMemcpyAsync(p_entA, entity_emb, entB_, cudaMemcpyDeviceToDevice, 0);
    cudaMemcpyAsync(p_usrA, user_emb,  usrB_, cudaMemcpyDeviceToDevice, 0);
    cudaMemcpyAsync(out, entity_emb, entB_, cudaMemcpyDeviceToDevice, 0);
    cudaMemcpyAsync(out + (size_t)N_ENT * D, user_emb, usrB_, cudaMemcpyDeviceToDevice, 0);

    for (int hop = 0; hop < 2; hop++) {
        const float* ein = (hop == 0) ? (const float*)p_entA : (const float*)p_entB;
        float*       eout = (hop == 0) ? (float*)p_entB : (float*)p_entA;
        const float* uin = (hop == 0) ? (const float*)p_usrA : (const float*)p_usrB;
        float*       uout = (hop == 0) ? (float*)p_usrB : (float*)p_usrA;

        // ---- entity LWS (all 3 virtual relations in one pass) ----
        for (int it = 0; it < 3; it++) {
            cudaMemsetAsync(p_acc, 0, (size_t)NVIRT * N_ENT * D * sizeof(float), 0);
            if (it == 0)      k_edge_ent<0><<<EB, TPB>>>(head, tail, ein);
            else if (it == 1) k_edge_ent<1><<<EB, TPB>>>(head, tail, ein);
            else              k_edge_ent<2><<<EB, TPB>>>(head, tail, ein);
            if (it < 2) k_row_sq_ent<<<RB3, TPB>>>(ein);
            else        k_row_final_ent<<<RB, TPB>>>(ein, eout, out, hop);
        }

        // ---- user LWS ----
        for (int it = 0; it < 3; it++) {
            cudaMemsetAsync(p_accu, 0, (size_t)N_USR * D * sizeof(float), 0);
            if (it == 0)      k_edge_usr<0><<<IB, TPB>>>(uidx, iidx, ein);
            else if (it == 1) k_edge_usr<1><<<IB, TPB>>>(uidx, iidx, ein);
            else              k_edge_usr<2><<<IB, TPB>>>(uidx, iidx, ein);
            if (it < 2) k_row_sq_usr<<<UB, TPB>>>(uin);
            else        k_row_final_usr<<<UB, TPB>>>(uin, uout, out + (size_t)N_ENT * D);
        }
    }
}

// round 3
// speedup vs baseline: 3.2956x; 3.2956x over previous
#include <cuda_runtime.h>
#include <math.h>

#define N_ENT 200000
#define N_USR 100000
#define D     64
#define NEDGE 1500000
#define NINT  1000000
#define NVIRT 3
#define NRELM1 10
#define NBKT  (NVIRT * N_ENT)
#define EPSV  1e-12f
#define SCAN_B 1024

// ---------------- scratch (static device globals) ----------------------------
__device__ float g_u[(size_t)NBKT * D];        // per-(virt,entity) LWS result u3
__device__ float g_entA[(size_t)N_ENT * D];
__device__ float g_entB[(size_t)N_ENT * D];
__device__ float g_usrA[(size_t)N_USR * D];
__device__ float g_usrB[(size_t)N_USR * D];
__device__ int   g_et[NEDGE];                  // virtual relation per edge
__device__ int   g_csr_tail[NEDGE];            // entity CSR values
__device__ int   g_csr_item[NINT];             // user CSR values
__device__ int   g_cntE[NBKT];
__device__ int   g_offE[NBKT];
__device__ int   g_curE[NBKT];
__device__ int   g_cntU[N_USR];
__device__ int   g_offU[N_USR];
__device__ int   g_curU[N_USR];
__device__ int   g_bsum[2048];
__device__ int   g_remap[NRELM1];
__device__ float g_w[2 * 3];

// ---------------- tiny prep ---------------------------------------------------
__global__ void k_prep(const float* __restrict__ latent,
                       const float* __restrict__ relw,
                       const float* __restrict__ aggw) {
    int t = threadIdx.x;
    if (t < NRELM1) {
        float best = -1e30f; int bi = 0;
        for (int v = 0; v < NVIRT; v++) {
            float s = 0.f;
            for (int d = 0; d < D; d++) s += relw[t * D + d] * latent[v * D + d];
            if (s > best) { best = s; bi = v; }
        }
        g_remap[t] = bi;
    }
    if (t >= 32 && t < 34) {
        int h = t - 32;
        float a0 = aggw[h * 3 + 0], a1 = aggw[h * 3 + 1], a2 = aggw[h * 3 + 2];
        float m = fmaxf(a0, fmaxf(a1, a2));
        float e0 = expf(a0 - m), e1 = expf(a1 - m), e2 = expf(a2 - m);
        float s = e0 + e1 + e2;
        g_w[h * 3 + 0] = e0 / s; g_w[h * 3 + 1] = e1 / s; g_w[h * 3 + 2] = e2 / s;
    }
}

__global__ void k_et(const int* __restrict__ etype) {
    int e = blockIdx.x * blockDim.x + threadIdx.x;
    if (e < NEDGE) g_et[e] = g_remap[etype[e] - 1];
}

// ---------------- CSR build: count -> exclusive scan -> scatter ---------------
__global__ void k_count_ent(const int* __restrict__ head) {
    int e = blockIdx.x * blockDim.x + threadIdx.x;
    if (e < NEDGE) atomicAdd(&g_cntE[g_et[e] * N_ENT + head[e]], 1);
}
__global__ void k_count_usr(const int* __restrict__ uidx) {
    int j = blockIdx.x * blockDim.x + threadIdx.x;
    if (j < NINT) atomicAdd(&g_cntU[uidx[j]], 1);
}

__global__ void k_scan1(const int* __restrict__ in, int* __restrict__ out,
                        int* __restrict__ bsum, int n) {
    __shared__ int sh[SCAN_B];
    int i = blockIdx.x * SCAN_B + threadIdx.x;
    int v = (i < n) ? in[i] : 0;
    sh[threadIdx.x] = v; __syncthreads();
    for (int o = 1; o < SCAN_B; o <<= 1) {
        int t = (threadIdx.x >= o) ? sh[threadIdx.x - o] : 0;
        __syncthreads();
        sh[threadIdx.x] += t;
        __syncthreads();
    }
    if (i < n) out[i] = sh[threadIdx.x] - v;          // exclusive
    if (threadIdx.x == SCAN_B - 1) bsum[blockIdx.x] = sh[threadIdx.x];
}
__global__ void k_scan2(int* __restrict__ bsum, int nb) {
    __shared__ int sh[SCAN_B];
    int v = (threadIdx.x < nb) ? bsum[threadIdx.x] : 0;
    sh[threadIdx.x] = v; __syncthreads();
    for (int o = 1; o < SCAN_B; o <<= 1) {
        int t = (threadIdx.x >= o) ? sh[threadIdx.x - o] : 0;
        __syncthreads();
        sh[threadIdx.x] += t;
        __syncthreads();
    }
    if (threadIdx.x < nb) bsum[threadIdx.x] = sh[threadIdx.x] - v;  // exclusive
}
__global__ void k_scan3(int* __restrict__ out, const int* __restrict__ bsum, int n) {
    int i = blockIdx.x * SCAN_B + threadIdx.x;
    if (i < n) out[i] += bsum[blockIdx.x];
}

__global__ void k_scatter_ent(const int* __restrict__ head, const int* __restrict__ tail) {
    int e = blockIdx.x * blockDim.x + threadIdx.x;
    if (e >= NEDGE) return;
    int b = g_et[e] * N_ENT + head[e];
    int pos = g_offE[b] + atomicAdd(&g_curE[b], 1);
    g_csr_tail[pos] = tail[e];
}
__global__ void k_scatter_usr(const int* __restrict__ uidx, const int* __restrict__ iidx) {
    int j = blockIdx.x * blockDim.x + threadIdx.x;
    if (j >= NINT) return;
    int b = uidx[j];
    int pos = g_offU[b] + atomicAdd(&g_curU[b], 1);
    g_csr_item[pos] = iidx[j];
}

// ---------------- helpers -----------------------------------------------------
__device__ __forceinline__ float warpdot2(float2 a, float2 b) {
    float p = a.x * b.x + a.y * b.y;
    #pragma unroll
    for (int o = 16; o; o >>= 1) p += __shfl_xor_sync(0xffffffffu, p, o);
    return p;
}
// squash(acc*inv) + e
__device__ __forceinline__ float2 squash_res(float2 acc, float inv, float2 e) {
    float2 a; a.x = acc.x * inv; a.y = acc.y * inv;
    float sq = warpdot2(a, a);
    float f = (sq / (sq + 1.0f)) / fmaxf(sqrtf(sq), EPSV);
    float2 r; r.x = a.x * f + e.x; r.y = a.y * f + e.y;
    return r;
}

// ---------------- entity LWS: one warp = one (virt,head) row, 3 iters fused ---
__global__ void k_lws_ent(const float* __restrict__ ent) {
    int row = (blockIdx.x * blockDim.x + threadIdx.x) >> 5;
    int lane = threadIdx.x & 31;
    if (row >= NBKT) return;
    int beg = g_offE[row];
    int end = (row + 1 < NBKT) ? g_offE[row + 1] : NEDGE;
    if (beg == end) return;                       // empty: final kernel uses ent row
    int i = row / N_ENT;
    int n = row - i * N_ENT;
    float inv = 1.0f / (float)(end - beg);
    float2 e = *(const float2*)(ent + (size_t)n * D + lane * 2);

    // iter 0: plain segment mean
    float2 acc; acc.x = 0.f; acc.y = 0.f;
    for (int j = beg; j < end; j++) {
        int t = g_csr_tail[j];
        float2 x = *(const float2*)(ent + (size_t)t * D + lane * 2);
        acc.x += x.x; acc.y += x.y;
    }
    float2 u1 = squash_res(acc, inv, e);

    // iter 1: coef = dot(u1, x)
    acc.x = 0.f; acc.y = 0.f;
    for (int j = beg; j < end; j++) {
        int t = g_csr_tail[j];
        float2 x = *(const float2*)(ent + (size_t)t * D + lane * 2);
        float p = warpdot2(u1, x);
        acc.x += p * x.x; acc.y += p * x.y;
    }
    float2 u2 = squash_res(acc, inv, e);

    // iter 2: coef = dot(u1,x)^2 * dot(u2,x); no squash
    acc.x = 0.f; acc.y = 0.f;
    for (int j = beg; j < end; j++) {
        int t = g_csr_tail[j];
        float2 x = *(const float2*)(ent + (size_t)t * D + lane * 2);
        float p1 = warpdot2(u1, x);
        float p2 = warpdot2(u2, x);
        float c = p1 * p1 * p2;
        acc.x += c * x.x; acc.y += c * x.y;
    }
    float2 u3; u3.x = acc.x * inv + e.x; u3.y = acc.y * inv + e.y;
    *(float2*)(g_u + (size_t)row * D + lane * 2) = u3;
}

// ---------------- entity final: weighted agg over virt + l2norm + residual ----
__global__ void k_final_ent(const float* __restrict__ ent, float* __restrict__ ent_out,
                            float* __restrict__ out, int hop) {
    int n = (blockIdx.x * blockDim.x + threadIdx.x) >> 5;
    int lane = threadIdx.x & 31;
    if (n >= N_ENT) return;
    float2 e = *(const float2*)(ent + (size_t)n * D + lane * 2);
    float2 agg; agg.x = 0.f; agg.y = 0.f;
    #pragma unroll
    for (int i = 0; i < NVIRT; i++) {
        int r = i * N_ENT + n;
        int beg = g_offE[r];
        int end = (r + 1 < NBKT) ? g_offE[r + 1] : NEDGE;
        float2 a;
        if (end > beg) a = *(const float2*)(g_u + (size_t)r * D + lane * 2);
        else           a = e;                     // empty row: u3 == ent row
        float wv = g_w[hop * 3 + i];
        agg.x += wv * a.x; agg.y += wv * a.y;
    }
    float sq = warpdot2(agg, agg);
    float f = 1.0f / fmaxf(sqrtf(sq), EPSV);
    float2 o2; o2.x = agg.x * f; o2.y = agg.y * f;
    *(float2*)(ent_out + (size_t)n * D + lane * 2) = o2;
    float* op = out + (size_t)n * D + lane * 2;
    float2 prev = *(float2*)op;
    prev.x += o2.x; prev.y += o2.y;
    *(float2*)op = prev;
}

// ---------------- user LWS: one warp = one user, fully fused -------------------
__global__ void k_lws_usr(const float* __restrict__ ent, const float* __restrict__ usr,
                          float* __restrict__ usr_out, float* __restrict__ out_usr) {
    int n = (blockIdx.x * blockDim.x + threadIdx.x) >> 5;
    int lane = threadIdx.x & 31;
    if (n >= N_USR) return;
    int beg = g_offU[n];
    int end = (n + 1 < N_USR) ? g_offU[n + 1] : NINT;
    float inv = 1.0f / fmaxf((float)(end - beg), 1.0f);
    float2 e = *(const float2*)(usr + (size_t)n * D + lane * 2);

    // iter 0
    float2 acc; acc.x = 0.f; acc.y = 0.f;
    for (int j = beg; j < end; j++) {
        int t = g_csr_item[j];
        float2 x = *(const float2*)(ent + (size_t)t * D + lane * 2);
        acc.x += x.x; acc.y += x.y;
    }
    float2 u = squash_res(acc, inv, e);

    // iter 1 (fresh sim each iteration)
    acc.x = 0.f; acc.y = 0.f;
    for (int j = beg; j < end; j++) {
        int t = g_csr_item[j];
        float2 x = *(const float2*)(ent + (size_t)t * D + lane * 2);
        float p = warpdot2(u, x);
        acc.x += p * x.x; acc.y += p * x.y;
    }
    u = squash_res(acc, inv, e);

    // iter 2 (no squash) + l2norm + residual, fused
    acc.x = 0.f; acc.y = 0.f;
    for (int j = beg; j < end; j++) {
        int t = g_csr_item[j];
        float2 x = *(const float2*)(ent + (size_t)t * D + lane * 2);
        float p = warpdot2(u, x);
        acc.x += p * x.x; acc.y += p * x.y;
    }
    float2 v; v.x = acc.x * inv + e.x; v.y = acc.y * inv + e.y;
    float sq = warpdot2(v, v);
    float f = 1.0f / fmaxf(sqrtf(sq), EPSV);
    float2 o2; o2.x = v.x * f; o2.y = v.y * f;
    *(float2*)(usr_out + (size_t)n * D + lane * 2) = o2;
    float* op = out_usr + (size_t)n * D + lane * 2;
    float2 prev = *(float2*)op;
    prev.x += o2.x; prev.y += o2.y;
    *(float2*)op = prev;
}

// ---------------- host orchestration ------------------------------------------
extern "C" void kernel_launch(void* const* d_in, const int* in_sizes, int n_in,
                              void* d_out, int out_size) {
    (void)in_sizes; (void)n_in; (void)out_size;
    const float* entity_emb = (const float*)d_in[0];
    const float* user_emb   = (const float*)d_in[1];
    const float* latent     = (const float*)d_in[2];
    const float* relw       = (const float*)d_in[3];
    const float* aggw       = (const float*)d_in[4];
    const int*   eidx       = (const int*)d_in[5];
    const int*   etype      = (const int*)d_in[6];
    const int*   uidx       = (const int*)d_in[7];
    const int*   iidx       = (const int*)d_in[8];
    float* out = (float*)d_out;
    const int* head = eidx;
    const int* tail = eidx + NEDGE;

    void *p_cntE, *p_offE, *p_curE, *p_cntU, *p_offU, *p_curU, *p_bsum;
    void *p_entA, *p_entB, *p_usrA, *p_usrB;
    cudaGetSymbolAddress(&p_cntE, g_cntE);
    cudaGetSymbolAddress(&p_offE, g_offE);
    cudaGetSymbolAddress(&p_curE, g_curE);
    cudaGetSymbolAddress(&p_cntU, g_cntU);
    cudaGetSymbolAddress(&p_offU, g_offU);
    cudaGetSymbolAddress(&p_curU, g_curU);
    cudaGetSymbolAddress(&p_bsum, g_bsum);
    cudaGetSymbolAddress(&p_entA, g_entA);
    cudaGetSymbolAddress(&p_entB, g_entB);
    cudaGetSymbolAddress(&p_usrA, g_usrA);
    cudaGetSymbolAddress(&p_usrB, g_usrB);

    const int TPB = 256;
    const int ET  = (NEDGE + TPB - 1) / TPB;
    const int IT_ = (NINT + TPB - 1) / TPB;
    const int NBE = (NBKT + SCAN_B - 1) / SCAN_B;      // 586
    const int NBU = (N_USR + SCAN_B - 1) / SCAN_B;     // 98
    const int LWB = (NBKT * 32 + TPB - 1) / TPB;
    const int RB  = (N_ENT * 32 + TPB - 1) / TPB;
    const int UB  = (N_USR * 32 + TPB - 1) / TPB;

    // prep + CSR build (stateless, recomputed every call)
    k_prep<<<1, 64>>>(latent, relw, aggw);
    k_et<<<ET, TPB>>>(etype);
    cudaMemsetAsync(p_cntE, 0, (size_t)NBKT * sizeof(int), 0);
    cudaMemsetAsync(p_cntU, 0, (size_t)N_USR * sizeof(int), 0);
    k_count_ent<<<ET, TPB>>>(head);
    k_count_usr<<<IT_, TPB>>>(uidx);
    k_scan1<<<NBE, SCAN_B>>>((const int*)p_cntE, (int*)p_offE, (int*)p_bsum, NBKT);
    k_scan2<<<1, SCAN_B>>>((int*)p_bsum, NBE);
    k_scan3<<<NBE, SCAN_B>>>((int*)p_offE, (const int*)p_bsum, NBKT);
    k_scan1<<<NBU, SCAN_B>>>((const int*)p_cntU, (int*)p_offU, (int*)p_bsum, N_USR);
    k_scan2<<<1, SCAN_B>>>((int*)p_bsum, NBU);
    k_scan3<<<NBU, SCAN_B>>>((int*)p_offU, (const int*)p_bsum, N_USR);
    cudaMemsetAsync(p_curE, 0, (size_t)NBKT * sizeof(int), 0);
    cudaMemsetAsync(p_curU, 0, (size_t)N_USR * sizeof(int), 0);
    k_scatter_ent<<<ET, TPB>>>(head, tail);
    k_scatter_usr<<<IT_, TPB>>>(uidx, iidx);

    size_t entB_ = (size_t)N_ENT * D * sizeof(float);
    size_t usrB_ = (size_t)N_USR * D * sizeof(float);
    cudaMemcpyAsync(p_entA, entity_emb, entB_, cudaMemcpyDeviceToDevice, 0);
    cudaMemcpyAsync(p_usrA, user_emb,  usrB_, cudaMemcpyDeviceToDevice, 0);
    cudaMemcpyAsync(out, entity_emb, entB_, cudaMemcpyDeviceToDevice, 0);
    cudaMemcpyAsync(out + (size_t)N_ENT * D, user_emb, usrB_, cudaMemcpyDeviceToDevice, 0);

    for (int hop = 0; hop < 2; hop++) {
        const float* ein  = (hop == 0) ? (const float*)p_entA : (const float*)p_entB;
        float*       eout = (hop == 0) ? (float*)p_entB : (float*)p_entA;
        const float* uin  = (hop == 0) ? (const float*)p_usrA : (const float*)p_usrB;
        float*       uout = (hop == 0) ? (float*)p_usrB : (float*)p_usrA;

        k_lws_ent<<<LWB, TPB>>>(ein);
        k_final_ent<<<RB, TPB>>>(ein, eout, out, hop);
        k_lws_usr<<<UB, TPB>>>(ein, uin, uout, out + (size_t)N_ENT * D);
    }
}

// round 5
// speedup vs baseline: 3.4150x; 1.0362x over previous
#include <cuda_runtime.h>
#include <math.h>

#define N_ENT 200000
#define N_USR 100000
#define D     64
#define NEDGE 1500000
#define NINT  1000000
#define NVIRT 3
#define NRELM1 10
#define NBKT  (NVIRT * N_ENT)
#define EPSV  1e-12f
#define SCAN_B 1024
#define CAP_E 12
#define CAP_U 20

// ---------------- scratch (static device globals) ----------------------------
__device__ float g_entB[(size_t)N_ENT * D];    // hop-0 entity output / hop-1 input
__device__ float g_entC[(size_t)N_ENT * D];    // hop-1 entity output (scratch)
__device__ float g_usrB[(size_t)N_USR * D];
__device__ float g_usrC[(size_t)N_USR * D];
__device__ int   g_csr_tail[NEDGE];
__device__ int   g_csr_item[NINT];
__device__ int   g_cntE[NBKT];
__device__ int   g_offE[NBKT];
__device__ int   g_curE[NBKT];
__device__ int   g_cntU[N_USR];
__device__ int   g_offU[N_USR];
__device__ int   g_curU[N_USR];
__device__ int   g_bsum[2048];
__device__ int   g_remap[NRELM1];
__device__ float g_w[2 * 3];

// ---------------- tiny prep ---------------------------------------------------
__global__ void k_prep(const float* __restrict__ latent,
                       const float* __restrict__ relw,
                       const float* __restrict__ aggw) {
    int t = threadIdx.x;
    if (t < NRELM1) {
        float best = -1e30f; int bi = 0;
        for (int v = 0; v < NVIRT; v++) {
            float s = 0.f;
            for (int d = 0; d < D; d++) s += relw[t * D + d] * latent[v * D + d];
            if (s > best) { best = s; bi = v; }
        }
        g_remap[t] = bi;
    }
    if (t >= 32 && t < 34) {
        int h = t - 32;
        float a0 = aggw[h * 3 + 0], a1 = aggw[h * 3 + 1], a2 = aggw[h * 3 + 2];
        float m = fmaxf(a0, fmaxf(a1, a2));
        float e0 = expf(a0 - m), e1 = expf(a1 - m), e2 = expf(a2 - m);
        float s = e0 + e1 + e2;
        g_w[h * 3 + 0] = e0 / s; g_w[h * 3 + 1] = e1 / s; g_w[h * 3 + 2] = e2 / s;
    }
}

// ---------------- CSR build ----------------------------------------------------
__global__ void k_count_ent(const int* __restrict__ head, const int* __restrict__ etype) {
    int e = blockIdx.x * blockDim.x + threadIdx.x;
    if (e < NEDGE) atomicAdd(&g_cntE[g_remap[etype[e] - 1] * N_ENT + head[e]], 1);
}
__global__ void k_count_usr(const int* __restrict__ uidx) {
    int j = blockIdx.x * blockDim.x + threadIdx.x;
    if (j < NINT) atomicAdd(&g_cntU[uidx[j]], 1);
}

__global__ void k_scan1(const int* __restrict__ in, int* __restrict__ out,
                        int* __restrict__ bsum, int n) {
    __shared__ int sh[SCAN_B];
    int i = blockIdx.x * SCAN_B + threadIdx.x;
    int v = (i < n) ? in[i] : 0;
    sh[threadIdx.x] = v; __syncthreads();
    for (int o = 1; o < SCAN_B; o <<= 1) {
        int t = (threadIdx.x >= o) ? sh[threadIdx.x - o] : 0;
        __syncthreads();
        sh[threadIdx.x] += t;
        __syncthreads();
    }
    if (i < n) out[i] = sh[threadIdx.x] - v;
    if (threadIdx.x == SCAN_B - 1) bsum[blockIdx.x] = sh[threadIdx.x];
}
__global__ void k_scan2(int* __restrict__ bsum, int nb) {
    __shared__ int sh[SCAN_B];
    int v = (threadIdx.x < nb) ? bsum[threadIdx.x] : 0;
    sh[threadIdx.x] = v; __syncthreads();
    for (int o = 1; o < SCAN_B; o <<= 1) {
        int t = (threadIdx.x >= o) ? sh[threadIdx.x - o] : 0;
        __syncthreads();
        sh[threadIdx.x] += t;
        __syncthreads();
    }
    if (threadIdx.x < nb) bsum[threadIdx.x] = sh[threadIdx.x] - v;
}
__global__ void k_scan3(int* __restrict__ out, const int* __restrict__ bsum, int n) {
    int i = blockIdx.x * SCAN_B + threadIdx.x;
    if (i < n) out[i] += bsum[blockIdx.x];
}

__global__ void k_scatter_ent(const int* __restrict__ head, const int* __restrict__ tail,
                              const int* __restrict__ etype) {
    int e = blockIdx.x * blockDim.x + threadIdx.x;
    if (e >= NEDGE) return;
    int b = g_remap[etype[e] - 1] * N_ENT + head[e];
    int pos = g_offE[b] + atomicAdd(&g_curE[b], 1);
    g_csr_tail[pos] = tail[e];
}
__global__ void k_scatter_usr(const int* __restrict__ uidx, const int* __restrict__ iidx) {
    int j = blockIdx.x * blockDim.x + threadIdx.x;
    if (j >= NINT) return;
    int b = uidx[j];
    int pos = g_offU[b] + atomicAdd(&g_curU[b], 1);
    g_csr_item[pos] = iidx[j];
}

// ---------------- helpers -----------------------------------------------------
__device__ __forceinline__ float warpdot2(float2 a, float2 b) {
    float p = a.x * b.x + a.y * b.y;
    #pragma unroll
    for (int o = 16; o; o >>= 1) p += __shfl_xor_sync(0xffffffffu, p, o);
    return p;
}
__device__ __forceinline__ float2 squash_res(float2 acc, float inv, float2 e) {
    float2 a; a.x = acc.x * inv; a.y = acc.y * inv;
    float sq = warpdot2(a, a);
    float f = (sq / (sq + 1.0f)) / fmaxf(sqrtf(sq), EPSV);
    float2 r; r.x = a.x * f + e.x; r.y = a.y * f + e.y;
    return r;
}

// ---------------- entity hop: LWS x3 virt + agg + l2norm + residual, fused ----
__global__ void __launch_bounds__(256) k_ent_hop(const float* __restrict__ ent,
                                                 float* __restrict__ ent_out,
                                                 float* __restrict__ out, int hop) {
    __shared__ float2 sh[8][CAP_E][32];          // 24 KB
    int gw = (blockIdx.x * blockDim.x + threadIdx.x) >> 5;
    int w = threadIdx.x >> 5;
    int lane = threadIdx.x & 31;
    if (gw >= N_ENT) return;
    int n = gw;
    float2 e = *(const float2*)(ent + (size_t)n * D + lane * 2);
    float2 agg; agg.x = 0.f; agg.y = 0.f;

    #pragma unroll
    for (int i = 0; i < NVIRT; i++) {
        int r = i * N_ENT + n;
        int beg = g_offE[r];
        int end = (r + 1 < NBKT) ? g_offE[r + 1] : NEDGE;
        int deg = end - beg;
        float2 u3;
        if (deg == 0) {
            u3 = e;
        } else {
            float inv = 1.0f / (float)deg;
            // iter 0: gather + cache
            float2 acc; acc.x = 0.f; acc.y = 0.f;
            for (int j = 0; j < deg; j++) {
                int t = g_csr_tail[beg + j];
                float2 x = *(const float2*)(ent + (size_t)t * D + lane * 2);
                if (j < CAP_E) sh[w][j][lane] = x;
                acc.x += x.x; acc.y += x.y;
            }
            float2 u1 = squash_res(acc, inv, e);
            // iter 1
            acc.x = 0.f; acc.y = 0.f;
            for (int j = 0; j < deg; j++) {
                float2 x;
                if (j < CAP_E) x = sh[w][j][lane];
                else {
                    int t = g_csr_tail[beg + j];
                    x = *(const float2*)(ent + (size_t)t * D + lane * 2);
                }
                float p = warpdot2(u1, x);
                acc.x += p * x.x; acc.y += p * x.y;
            }
            float2 u2 = squash_res(acc, inv, e);
            // iter 2
            acc.x = 0.f; acc.y = 0.f;
            for (int j = 0; j < deg; j++) {
                float2 x;
                if (j < CAP_E) x = sh[w][j][lane];
                else {
                    int t = g_csr_tail[beg + j];
                    x = *(const float2*)(ent + (size_t)t * D + lane * 2);
                }
                float p1 = warpdot2(u1, x);
                float p2 = warpdot2(u2, x);
                float c = p1 * p1 * p2;
                acc.x += c * x.x; acc.y += c * x.y;
            }
            u3.x = acc.x * inv + e.x; u3.y = acc.y * inv + e.y;
        }
        float wv = g_w[hop * 3 + i];
        agg.x += wv * u3.x; agg.y += wv * u3.y;
    }

    float sq = warpdot2(agg, agg);
    float f = 1.0f / fmaxf(sqrtf(sq), EPSV);
    float2 o2; o2.x = agg.x * f; o2.y = agg.y * f;
    *(float2*)(ent_out + (size_t)n * D + lane * 2) = o2;
    float* op = out + (size_t)n * D + lane * 2;
    if (hop == 0) {                   // out = orig ent + o2 (ent IS orig on hop 0)
        float2 v; v.x = e.x + o2.x; v.y = e.y + o2.y;
        *(float2*)op = v;
    } else {
        float2 prev = *(float2*)op;
        prev.x += o2.x; prev.y += o2.y;
        *(float2*)op = prev;
    }
}

// ---------------- user hop: fully fused ---------------------------------------
__global__ void __launch_bounds__(256) k_usr_hop(const float* __restrict__ ent,
                                                 const float* __restrict__ usr,
                                                 float* __restrict__ usr_out,
                                                 float* __restrict__ out_usr, int hop) {
    __shared__ float2 sh[8][CAP_U][32];          // 40 KB
    int gw = (blockIdx.x * blockDim.x + threadIdx.x) >> 5;
    int w = threadIdx.x >> 5;
    int lane = threadIdx.x & 31;
    if (gw >= N_USR) return;
    int n = gw;
    int beg = g_offU[n];
    int end = (n + 1 < N_USR) ? g_offU[n + 1] : NINT;
    int deg = end - beg;
    float inv = 1.0f / fmaxf((float)deg, 1.0f);
    float2 e = *(const float2*)(usr + (size_t)n * D + lane * 2);

    // iter 0: gather + cache
    float2 acc; acc.x = 0.f; acc.y = 0.f;
    for (int j = 0; j < deg; j++) {
        int t = g_csr_item[beg + j];
        float2 x = *(const float2*)(ent + (size_t)t * D + lane * 2);
        if (j < CAP_U) sh[w][j][lane] = x;
        acc.x += x.x; acc.y += x.y;
    }
    float2 u = squash_res(acc, inv, e);

    // iter 1
    acc.x = 0.f; acc.y = 0.f;
    for (int j = 0; j < deg; j++) {
        float2 x;
        if (j < CAP_U) x = sh[w][j][lane];
        else {
            int t = g_csr_item[beg + j];
            x = *(const float2*)(ent + (size_t)t * D + lane * 2);
        }
        float p = warpdot2(u, x);
        acc.x += p * x.x; acc.y += p * x.y;
    }
    u = squash_res(acc, inv, e);

    // iter 2 + l2norm + residual
    acc.x = 0.f; acc.y = 0.f;
    for (int j = 0; j < deg; j++) {
        float2 x;
        if (j < CAP_U) x = sh[w][j][lane];
        else {
            int t = g_csr_item[beg + j];
            x = *(const float2*)(ent + (size_t)t * D + lane * 2);
        }
        float p = warpdot2(u, x);
        acc.x += p * x.x; acc.y += p * x.y;
    }
    float2 v; v.x = acc.x * inv + e.x; v.y = acc.y * inv + e.y;
    float sq = warpdot2(v, v);
    float f = 1.0f / fmaxf(sqrtf(sq), EPSV);
    float2 o2; o2.x = v.x * f; o2.y = v.y * f;
    *(float2*)(usr_out + (size_t)n * D + lane * 2) = o2;
    float* op = out_usr + (size_t)n * D + lane * 2;
    if (hop == 0) {
        float2 ov; ov.x = e.x + o2.x; ov.y = e.y + o2.y;
        *(float2*)op = ov;
    } else {
        float2 prev = *(float2*)op;
        prev.x += o2.x; prev.y += o2.y;
        *(float2*)op = prev;
    }
}

// ---------------- host orchestration ------------------------------------------
extern "C" void kernel_launch(void* const* d_in, const int* in_sizes, int n_in,
                              void* d_out, int out_size) {
    (void)in_sizes; (void)n_in; (void)out_size;
    const float* entity_emb = (const float*)d_in[0];
    const float* user_emb   = (const float*)d_in[1];
    const float* latent     = (const float*)d_in[2];
    const float* relw       = (const float*)d_in[3];
    const float* aggw       = (const float*)d_in[4];
    const int*   eidx       = (const int*)d_in[5];
    const int*   etype      = (const int*)d_in[6];
    const int*   uidx       = (const int*)d_in[7];
    const int*   iidx       = (const int*)d_in[8];
    float* out = (float*)d_out;
    const int* head = eidx;
    const int* tail = eidx + NEDGE;

    void *p_cntE, *p_offE, *p_curE, *p_cntU, *p_offU, *p_curU, *p_bsum;
    void *p_entB, *p_entC, *p_usrB, *p_usrC;
    cudaGetSymbolAddress(&p_cntE, g_cntE);
    cudaGetSymbolAddress(&p_offE, g_offE);
    cudaGetSymbolAddress(&p_curE, g_curE);
    cudaGetSymbolAddress(&p_cntU, g_cntU);
    cudaGetSymbolAddress(&p_offU, g_offU);
    cudaGetSymbolAddress(&p_curU, g_curU);
    cudaGetSymbolAddress(&p_bsum, g_bsum);
    cudaGetSymbolAddress(&p_entB, g_entB);
    cudaGetSymbolAddress(&p_entC, g_entC);
    cudaGetSymbolAddress(&p_usrB, g_usrB);
    cudaGetSymbolAddress(&p_usrC, g_usrC);

    const int TPB = 256;
    const int ET  = (NEDGE + TPB - 1) / TPB;
    const int IT_ = (NINT + TPB - 1) / TPB;
    const int NBE = (NBKT + SCAN_B - 1) / SCAN_B;
    const int NBU = (N_USR + SCAN_B - 1) / SCAN_B;
    const int RB  = (N_ENT * 32 + TPB - 1) / TPB;
    const int UB  = (N_USR * 32 + TPB - 1) / TPB;

    // prep + CSR build
    k_prep<<<1, 64>>>(latent, relw, aggw);
    cudaMemsetAsync(p_cntE, 0, (size_t)NBKT * sizeof(int), 0);
    cudaMemsetAsync(p_cntU, 0, (size_t)N_USR * sizeof(int), 0);
    k_count_ent<<<ET, TPB>>>(head, etype);
    k_count_usr<<<IT_, TPB>>>(uidx);
    k_scan1<<<NBE, SCAN_B>>>((const int*)p_cntE, (int*)p_offE, (int*)p_bsum, NBKT);
    k_scan2<<<1, SCAN_B>>>((int*)p_bsum, NBE);
    k_scan3<<<NBE, SCAN_B>>>((int*)p_offE, (const int*)p_bsum, NBKT);
    k_scan1<<<NBU, SCAN_B>>>((const int*)p_cntU, (int*)p_offU, (int*)p_bsum, N_USR);
    k_scan2<<<1, SCAN_B>>>((int*)p_bsum, NBU);
    k_scan3<<<NBU, SCAN_B>>>((int*)p_offU, (const int*)p_bsum, N_USR);
    cudaMemsetAsync(p_curE, 0, (size_t)NBKT * sizeof(int), 0);
    cudaMemsetAsync(p_curU, 0, (size_t)N_USR * sizeof(int), 0);
    k_scatter_ent<<<ET, TPB>>>(head, tail, etype);
    k_scatter_usr<<<IT_, TPB>>>(uidx, iidx);

    // hop 0: read original embeddings directly
    k_ent_hop<<<RB, TPB>>>(entity_emb, (float*)p_entB, out, 0);
    k_usr_hop<<<UB, TPB>>>(entity_emb, user_emb, (float*)p_usrB, out + (size_t)N_ENT * D, 0);
    // hop 1
    k_ent_hop<<<RB, TPB>>>((const float*)p_entB, (float*)p_entC, out, 1);
    k_usr_hop<<<UB, TPB>>>((const float*)p_entB, (const float*)p_usrB, (float*)p_usrC,
                           out + (size_t)N_ENT * D, 1);
}